// round 1
// baseline (speedup 1.0000x reference)
#include <cuda_runtime.h>
#include <cstdint>

#define GN 10000   // nodes
#define GE 64000   // edges
#define GG 64      // graphs
#define HH 64      // hidden
#define XD 128     // input feat
#define EAD 32     // edge attr dim
#define KTOT 4224  // 4096 (S outer) + 64 (sh @ B2) + 64 (h @ root)

// ---------------- scratch (static device memory; no allocs allowed) ----------
__device__ float g_hx[GN * HH];                    // node features (in-place per layer)
__device__ float g_hidden[GE * HH];                // edge MLP hidden (relu(ea@w1+b1))
__device__ float g_S[(size_t)GN * KTOT];           // per-node bilinear accumulators + sh + h
__device__ float g_Bcat[KTOT * HH];                // [w2 as 4096x64 ; B2 ; root]
__device__ int   g_cnt[GN];
__device__ int   g_off[GN + 1];
__device__ int   g_cur[GN];
__device__ int   g_sorted[GE];
__device__ float g_hg[GG * HH];
__device__ int   g_e64;                            // edge_index is int64?
__device__ int   g_b64;                            // batch is int64?

__device__ __forceinline__ long long ld_idx(const void* p, long long i, int is64) {
    return is64 ? ((const long long*)p)[i] : (long long)((const int*)p)[i];
}
__device__ __forceinline__ float lrelu(float v) { return v >= 0.f ? v : 0.01f * v; }

// ---------------- dtype detection (int64 vs int32, decided on-device) --------
__global__ void k_detect(const void* eidx, const void* batch) {
    if (threadIdx.x != 0 || blockIdx.x != 0) return;
    const long long* p = (const long long*)eidx;
    int e64 = 1;
    for (int i = 0; i < 128; i++) {
        long long v = p[i];
        if (v < 0 || v >= GN) { e64 = 0; break; }
    }
    g_e64 = e64;
    const long long* b = (const long long*)batch;
    int b64 = 1;
    // check mid-range entries: in-bounds for both dtypes, values nonzero there
    for (int i = GN / 2 - 64; i < GN / 2; i++) {
        long long v = b[i];
        if (v < 0 || v >= GG) { b64 = 0; break; }
    }
    g_b64 = b64;
}

__global__ void k_zero() {
    int i = blockIdx.x * 256 + threadIdx.x;
    if (i < GN) { g_cnt[i] = 0; g_cur[i] = 0; }
    if (i < GG * HH) g_hg[i] = 0.f;
}

// ---------------- node encoder: hx = lrelu(x @ nfc_w + nfc_b) ----------------
__global__ __launch_bounds__(256) void k_nodefc(const float* __restrict__ x,
                                                const float* __restrict__ w,
                                                const float* __restrict__ b) {
    __shared__ float xs[4][XD];
    int n0 = blockIdx.x * 4;
    int t = threadIdx.x;
#pragma unroll
    for (int q = 0; q < 2; q++) {
        int idx = t + q * 256;
        xs[idx >> 7][idx & 127] = x[(size_t)(n0 + (idx >> 7)) * XD + (idx & 127)];
    }
    __syncthreads();
    int ln = t >> 6, o = t & 63;
    float acc = b[o];
#pragma unroll
    for (int k = 0; k < XD; k++) acc = fmaf(xs[ln][k], w[k * HH + o], acc);
    g_hx[(size_t)(n0 + ln) * HH + o] = lrelu(acc);
}

// ---------------- CSR build (counting sort by dst, deterministic) ------------
__global__ void k_hist(const void* eidx) {
    int e = blockIdx.x * 256 + threadIdx.x;
    if (e >= GE) return;
    int d = (int)ld_idx(eidx, (long long)GE + e, g_e64);
    atomicAdd(&g_cnt[d], 1);
}

__global__ __launch_bounds__(1024) void k_scan() {
    __shared__ int part[1024];
    const int C = 10;
    int t = threadIdx.x;
    int base = t * C;
    int loc[C];
    int s = 0;
#pragma unroll
    for (int j = 0; j < C; j++) {
        int idx = base + j;
        int c = (idx < GN) ? g_cnt[idx] : 0;
        loc[j] = s;
        s += c;
    }
    part[t] = s;
    __syncthreads();
    for (int off = 1; off < 1024; off <<= 1) {
        int v = (t >= off) ? part[t - off] : 0;
        __syncthreads();
        part[t] += v;
        __syncthreads();
    }
    int pre = part[t] - s;  // exclusive prefix
#pragma unroll
    for (int j = 0; j < C; j++) {
        int idx = base + j;
        if (idx <= GN) g_off[idx] = pre + loc[j];
    }
}

__global__ void k_fill(const void* eidx) {
    int e = blockIdx.x * 256 + threadIdx.x;
    if (e >= GE) return;
    int d = (int)ld_idx(eidx, (long long)GE + e, g_e64);
    int pos = g_off[d] + atomicAdd(&g_cur[d], 1);
    g_sorted[pos] = e;
}

__global__ void k_sortnode() {
    int n = blockIdx.x * 128 + threadIdx.x;
    if (n >= GN) return;
    int b = g_off[n], e = g_off[n + 1];
    for (int i = b + 1; i < e; i++) {
        int v = g_sorted[i];
        int j = i - 1;
        while (j >= b && g_sorted[j] > v) { g_sorted[j + 1] = g_sorted[j]; j--; }
        g_sorted[j + 1] = v;
    }
}

// ---------------- B matrix concat: [w2(4096x64); B2(64x64); root(64x64)] -----
__global__ void k_prepB(const float* __restrict__ w2, const float* __restrict__ b2,
                        const float* __restrict__ root) {
    int idx = blockIdx.x * 256 + threadIdx.x;
    if (idx >= KTOT * HH) return;
    int r = idx >> 6, o = idx & 63;
    float v;
    if (r < 4096)       v = w2[idx];                     // (k*64+i)*64+o == k*4096+i*64+o
    else if (r < 4160)  v = b2[(r - 4096) * HH + o];
    else                v = root[(r - 4160) * HH + o];
    g_Bcat[idx] = v;
}

// ---------------- edge MLP hidden: relu(ea @ w1 + b1) ------------------------
__global__ __launch_bounds__(256) void k_hidden(const float* __restrict__ ea,
                                                const float* __restrict__ w1,
                                                const float* __restrict__ b1) {
    __shared__ float eas[4][EAD];
    int e0 = blockIdx.x * 4;
    int t = threadIdx.x;
    if (t < 128) eas[t >> 5][t & 31] = ea[(size_t)(e0 + (t >> 5)) * EAD + (t & 31)];
    __syncthreads();
    int le = t >> 6, o = t & 63;
    float acc = b1[o];
#pragma unroll
    for (int k = 0; k < EAD; k++) acc = fmaf(eas[le][k], w1[k * HH + o], acc);
    g_hidden[(size_t)(e0 + le) * HH + o] = fmaxf(acc, 0.f);
}

// ---------------- per-node S row: outer-product accumulation -----------------
// S[n, k*64+i] = sum_{e:dst=n} hidden[e,k]*hx[src[e],i];  S[n,4096+i]=sum hx_src; S[n,4160+i]=hx[n,i]
__global__ __launch_bounds__(128) void k_S(const void* eidx) {
    int n = blockIdx.x;
    int t = threadIdx.x;
    int k = t >> 1, half = t & 1;
    __shared__ float hid_s[64], hsrc_s[64];
    float acc[32];
#pragma unroll
    for (int q = 0; q < 32; q++) acc[q] = 0.f;
    float shacc = 0.f;
    int beg = g_off[n], end = g_off[n + 1];
    int is64 = g_e64;
    for (int j = beg; j < end; j++) {
        int e = g_sorted[j];
        long long s = ld_idx(eidx, e, is64);  // src
        if (t < 64) hid_s[t] = g_hidden[(size_t)e * HH + t];
        else        hsrc_s[t - 64] = g_hx[(size_t)s * HH + (t - 64)];
        __syncthreads();
        float c = hid_s[k];
        const float* hp = &hsrc_s[half * 32];
#pragma unroll
        for (int q = 0; q < 32; q++) acc[q] = fmaf(c, hp[q], acc[q]);
        if (t < 64) shacc += hsrc_s[t];
        __syncthreads();
    }
    size_t base = (size_t)n * KTOT;
#pragma unroll
    for (int q = 0; q < 32; q += 4) {
        float4 v = make_float4(acc[q], acc[q + 1], acc[q + 2], acc[q + 3]);
        *(float4*)&g_S[base + k * 64 + half * 32 + q] = v;
    }
    if (t < 64) g_S[base + 4096 + t] = shacc;
    else        g_S[base + 4160 + (t - 64)] = g_hx[(size_t)n * HH + (t - 64)];
}

// ---------------- GEMM: hx = lrelu(S @ Bcat + gc_bias)  [10000,4224]x[4224,64]
__global__ __launch_bounds__(256) void k_gemm(const float* __restrict__ bias) {
    __shared__ float As[64][36];   // [m][kk], padded stride 36 (144B, 16B-aligned)
    __shared__ float Bs[32][64];   // [kk][o]
    int t = threadIdx.x;
    int m0 = blockIdx.x * 64;
    int tx = t & 15, ty = t >> 4;
    float acc[4][4];
#pragma unroll
    for (int i = 0; i < 4; i++)
#pragma unroll
        for (int j = 0; j < 4; j++) acc[i][j] = 0.f;

    for (int k0 = 0; k0 < KTOT; k0 += 32) {
#pragma unroll
        for (int q = 0; q < 2; q++) {
            int idx = t + q * 256;        // 0..511: 64 rows x 8 float4
            int r = idx >> 3, c4 = idx & 7;
            int row = m0 + r;
            float4 v = make_float4(0.f, 0.f, 0.f, 0.f);
            if (row < GN) v = *(const float4*)&g_S[(size_t)row * KTOT + k0 + c4 * 4];
            *(float4*)&As[r][c4 * 4] = v;
        }
#pragma unroll
        for (int q = 0; q < 2; q++) {
            int idx = t + q * 256;        // 0..511: 32 rows x 16 float4
            int kk = idx >> 4, c4 = idx & 15;
            *(float4*)&Bs[kk][c4 * 4] = *(const float4*)&g_Bcat[(k0 + kk) * 64 + c4 * 4];
        }
        __syncthreads();
#pragma unroll 8
        for (int kk = 0; kk < 32; kk++) {
            float4 bv = *(const float4*)&Bs[kk][tx * 4];
            float a0 = As[ty * 4 + 0][kk];
            float a1 = As[ty * 4 + 1][kk];
            float a2 = As[ty * 4 + 2][kk];
            float a3 = As[ty * 4 + 3][kk];
            acc[0][0] = fmaf(a0, bv.x, acc[0][0]); acc[0][1] = fmaf(a0, bv.y, acc[0][1]);
            acc[0][2] = fmaf(a0, bv.z, acc[0][2]); acc[0][3] = fmaf(a0, bv.w, acc[0][3]);
            acc[1][0] = fmaf(a1, bv.x, acc[1][0]); acc[1][1] = fmaf(a1, bv.y, acc[1][1]);
            acc[1][2] = fmaf(a1, bv.z, acc[1][2]); acc[1][3] = fmaf(a1, bv.w, acc[1][3]);
            acc[2][0] = fmaf(a2, bv.x, acc[2][0]); acc[2][1] = fmaf(a2, bv.y, acc[2][1]);
            acc[2][2] = fmaf(a2, bv.z, acc[2][2]); acc[2][3] = fmaf(a2, bv.w, acc[2][3]);
            acc[3][0] = fmaf(a3, bv.x, acc[3][0]); acc[3][1] = fmaf(a3, bv.y, acc[3][1]);
            acc[3][2] = fmaf(a3, bv.z, acc[3][2]); acc[3][3] = fmaf(a3, bv.w, acc[3][3]);
        }
        __syncthreads();
    }
#pragma unroll
    for (int i = 0; i < 4; i++) {
        int row = m0 + ty * 4 + i;
        if (row < GN) {
            int col = tx * 4;
            float4 o;
            o.x = lrelu(acc[i][0] + bias[col + 0]);
            o.y = lrelu(acc[i][1] + bias[col + 1]);
            o.z = lrelu(acc[i][2] + bias[col + 2]);
            o.w = lrelu(acc[i][3] + bias[col + 3]);
            *(float4*)&g_hx[(size_t)row * HH + col] = o;
        }
    }
}

// ---------------- global_add_pool + head -------------------------------------
__global__ void k_pool(const void* batch) {
    int t = threadIdx.x;
    int n = blockIdx.x * 4 + (t >> 6);
    int o = t & 63;
    int g = (int)ld_idx(batch, n, g_b64);
    atomicAdd(&g_hg[g * HH + o], g_hx[(size_t)n * HH + o]);
}

__global__ void k_head(const float* __restrict__ fc1w, const float* __restrict__ fc1b,
                       const float* __restrict__ fc2w, const float* __restrict__ fc2b,
                       float* __restrict__ out) {
    int g = threadIdx.x;
    if (g >= GG) return;
    float h[64];
#pragma unroll
    for (int i = 0; i < 64; i++) h[i] = g_hg[g * 64 + i];
    float o = fc2b[0];
    for (int j = 0; j < 32; j++) {
        float s = fc1b[j];
#pragma unroll
        for (int i = 0; i < 64; i++) s = fmaf(h[i], fc1w[i * 32 + j], s);
        o = fmaf(lrelu(s), fc2w[j], o);
    }
    out[g] = o;
}

// ---------------- launch ------------------------------------------------------
extern "C" void kernel_launch(void* const* d_in, const int* in_sizes, int n_in,
                              void* d_out, int out_size) {
    const float* x     = (const float*)d_in[0];
    const void*  eidx  = d_in[1];
    const float* ea    = (const float*)d_in[2];
    const void*  batch = d_in[3];
    const float* nfc_w = (const float*)d_in[4];
    const float* nfc_b = (const float*)d_in[5];
    const float* e1w1  = (const float*)d_in[6];
    const float* e1b1  = (const float*)d_in[7];
    const float* e1w2  = (const float*)d_in[8];
    const float* e1b2  = (const float*)d_in[9];
    const float* g1root= (const float*)d_in[10];
    const float* g1bias= (const float*)d_in[11];
    const float* e2w1  = (const float*)d_in[12];
    const float* e2b1  = (const float*)d_in[13];
    const float* e2w2  = (const float*)d_in[14];
    const float* e2b2  = (const float*)d_in[15];
    const float* g2root= (const float*)d_in[16];
    const float* g2bias= (const float*)d_in[17];
    const float* fc1w  = (const float*)d_in[18];
    const float* fc1b  = (const float*)d_in[19];
    const float* fc2w  = (const float*)d_in[20];
    const float* fc2b  = (const float*)d_in[21];
    float* out = (float*)d_out;

    k_detect<<<1, 32>>>(eidx, batch);
    k_zero<<<(GN + 255) / 256, 256>>>();
    k_nodefc<<<GN / 4, 256>>>(x, nfc_w, nfc_b);
    k_hist<<<GE / 256, 256>>>(eidx);
    k_scan<<<1, 1024>>>();
    k_fill<<<GE / 256, 256>>>(eidx);
    k_sortnode<<<(GN + 127) / 128, 128>>>();

    // layer 1
    k_prepB<<<(KTOT * HH + 255) / 256, 256>>>(e1w2, e1b2, g1root);
    k_hidden<<<GE / 4, 256>>>(ea, e1w1, e1b1);
    k_S<<<GN, 128>>>(eidx);
    k_gemm<<<(GN + 63) / 64, 256>>>(g1bias);

    // layer 2
    k_prepB<<<(KTOT * HH + 255) / 256, 256>>>(e2w2, e2b2, g2root);
    k_hidden<<<GE / 4, 256>>>(ea, e2w1, e2b1);
    k_S<<<GN, 128>>>(eidx);
    k_gemm<<<(GN + 63) / 64, 256>>>(g2bias);

    k_pool<<<GN / 4, 256>>>(batch);
    k_head<<<1, 64>>>(fc1w, fc1b, fc2w, fc2b, out);
}

// round 3
// speedup vs baseline: 1.0419x; 1.0419x over previous
#include <cuda_runtime.h>
#include <cstdint>

#define GN 10000   // nodes
#define GE 64000   // edges
#define GG 64      // graphs
#define HH 64      // hidden
#define XD 128     // input feat
#define EAD 32     // edge attr dim
#define KTOT 4224  // 4096 (S outer) + 64 (sh @ B2) + 64 (h @ root)

// ---------------- scratch (static device memory; no allocs allowed) ----------
__device__ float g_hx[GN * HH];                    // node features (in-place per layer)
__device__ float g_hidden[GE * HH];                // edge MLP hidden (relu(ea@w1+b1))
__device__ float g_S[(size_t)GN * KTOT];           // per-node bilinear accumulators + sh + h
__device__ float g_Bcat[KTOT * HH];                // [w2 as 4096x64 ; B2 ; root], row-major [k][o]
__device__ int   g_cnt[GN];
__device__ int   g_off[GN + 1];
__device__ int   g_cur[GN];
__device__ int   g_sorted[GE];
__device__ float g_hg[GG * HH];
__device__ int   g_e64;                            // edge_index is int64?
__device__ int   g_b64;                            // batch is int64?

__device__ __forceinline__ long long ld_idx(const void* p, long long i, int is64) {
    return is64 ? ((const long long*)p)[i] : (long long)((const int*)p)[i];
}
__device__ __forceinline__ float lrelu(float v) { return v >= 0.f ? v : 0.01f * v; }

// ---- packed f32x2 helpers (Blackwell FFMA2; base sm_100 PTX) -----------------
__device__ __forceinline__ uint64_t pack2(float x, float y) {
    uint64_t r;
    asm("mov.b64 %0, {%1, %2};" : "=l"(r) : "f"(x), "f"(y));
    return r;
}
__device__ __forceinline__ void unpack2(uint64_t v, float& x, float& y) {
    asm("mov.b64 {%0, %1}, %2;" : "=f"(x), "=f"(y) : "l"(v));
}
__device__ __forceinline__ void ffma2(uint64_t& acc, uint64_t a, uint64_t b) {
    asm("fma.rn.f32x2 %0, %1, %2, %0;" : "+l"(acc) : "l"(a), "l"(b));
}

// ---------------- dtype detection (parallel, one warp) -----------------------
__global__ void k_detect(const void* eidx, const void* batch) {
    int t = threadIdx.x;  // 32 threads
    const long long* p = (const long long*)eidx;
    bool ok = true;
#pragma unroll
    for (int j = 0; j < 4; j++) {
        long long v = p[t + j * 32];
        ok &= (v >= 0 && v < GN);
    }
    unsigned e_ok = __all_sync(0xFFFFFFFFu, ok);
    const long long* b = (const long long*)batch;
    bool okb = true;
#pragma unroll
    for (int j = 0; j < 2; j++) {
        long long v = b[GN / 2 - 64 + t + j * 32];
        okb &= (v >= 0 && v < GG);
    }
    unsigned b_ok = __all_sync(0xFFFFFFFFu, okb);
    if (t == 0) { g_e64 = e_ok ? 1 : 0; g_b64 = b_ok ? 1 : 0; }
}

__global__ void k_zero() {
    int i = blockIdx.x * 256 + threadIdx.x;
    if (i < GN) { g_cnt[i] = 0; g_cur[i] = 0; }
    if (i < GG * HH) g_hg[i] = 0.f;
}

// ---------------- node encoder: hx = lrelu(x @ nfc_w + nfc_b) ----------------
__global__ __launch_bounds__(256) void k_nodefc(const float* __restrict__ x,
                                                const float* __restrict__ w,
                                                const float* __restrict__ b) {
    __shared__ float xs[4][XD];
    int n0 = blockIdx.x * 4;
    int t = threadIdx.x;
#pragma unroll
    for (int q = 0; q < 2; q++) {
        int idx = t + q * 256;
        xs[idx >> 7][idx & 127] = x[(size_t)(n0 + (idx >> 7)) * XD + (idx & 127)];
    }
    __syncthreads();
    int ln = t >> 6, o = t & 63;
    float acc = b[o];
#pragma unroll
    for (int k = 0; k < XD; k++) acc = fmaf(xs[ln][k], w[k * HH + o], acc);
    g_hx[(size_t)(n0 + ln) * HH + o] = lrelu(acc);
}

// ---------------- CSR build (counting sort by dst, deterministic) ------------
__global__ void k_hist(const void* eidx) {
    int e = blockIdx.x * 256 + threadIdx.x;
    if (e >= GE) return;
    int d = (int)ld_idx(eidx, (long long)GE + e, g_e64);
    atomicAdd(&g_cnt[d], 1);
}

__global__ __launch_bounds__(1024) void k_scan() {
    __shared__ int part[1024];
    const int C = 10;
    int t = threadIdx.x;
    int base = t * C;
    int loc[C];
    int s = 0;
#pragma unroll
    for (int j = 0; j < C; j++) {
        int idx = base + j;
        int c = (idx < GN) ? g_cnt[idx] : 0;
        loc[j] = s;
        s += c;
    }
    part[t] = s;
    __syncthreads();
    for (int off = 1; off < 1024; off <<= 1) {
        int v = (t >= off) ? part[t - off] : 0;
        __syncthreads();
        part[t] += v;
        __syncthreads();
    }
    int pre = part[t] - s;  // exclusive prefix
#pragma unroll
    for (int j = 0; j < C; j++) {
        int idx = base + j;
        if (idx <= GN) g_off[idx] = pre + loc[j];
    }
}

__global__ void k_fill(const void* eidx) {
    int e = blockIdx.x * 256 + threadIdx.x;
    if (e >= GE) return;
    int d = (int)ld_idx(eidx, (long long)GE + e, g_e64);
    int pos = g_off[d] + atomicAdd(&g_cur[d], 1);
    g_sorted[pos] = e;
}

__global__ void k_sortnode() {
    int n = blockIdx.x * 128 + threadIdx.x;
    if (n >= GN) return;
    int b = g_off[n], e = g_off[n + 1];
    for (int i = b + 1; i < e; i++) {
        int v = g_sorted[i];
        int j = i - 1;
        while (j >= b && g_sorted[j] > v) { g_sorted[j + 1] = g_sorted[j]; j--; }
        g_sorted[j + 1] = v;
    }
}

// ---------------- B matrix concat: [w2(4096x64); B2(64x64); root(64x64)] -----
__global__ void k_prepB(const float* __restrict__ w2, const float* __restrict__ b2,
                        const float* __restrict__ root) {
    int idx = blockIdx.x * 256 + threadIdx.x;
    if (idx >= KTOT * HH) return;
    int r = idx >> 6, o = idx & 63;
    float v;
    if (r < 4096)       v = w2[idx];                     // (k*64+i)*64+o == k*4096+i*64+o
    else if (r < 4160)  v = b2[(r - 4096) * HH + o];
    else                v = root[(r - 4160) * HH + o];
    g_Bcat[idx] = v;
}

// ---------------- edge MLP hidden: relu(ea @ w1 + b1) ------------------------
__global__ __launch_bounds__(256) void k_hidden(const float* __restrict__ ea,
                                                const float* __restrict__ w1,
                                                const float* __restrict__ b1) {
    __shared__ float eas[4][EAD];
    int e0 = blockIdx.x * 4;
    int t = threadIdx.x;
    if (t < 128) eas[t >> 5][t & 31] = ea[(size_t)(e0 + (t >> 5)) * EAD + (t & 31)];
    __syncthreads();
    int le = t >> 6, o = t & 63;
    float acc = b1[o];
#pragma unroll
    for (int k = 0; k < EAD; k++) acc = fmaf(eas[le][k], w1[k * HH + o], acc);
    g_hidden[(size_t)(e0 + le) * HH + o] = fmaxf(acc, 0.f);
}

// ---------------- per-node S row: outer-product accumulation -----------------
// S[n, k*64+i] = sum_{e:dst=n} hidden[e,k]*hx[src[e],i];  S[n,4096+i]=sum hx_src; S[n,4160+i]=hx[n,i]
__global__ __launch_bounds__(128) void k_S(const void* eidx) {
    int n = blockIdx.x;
    int t = threadIdx.x;
    int k = t >> 1, half = t & 1;
    __shared__ float hid_s[64], hsrc_s[64];
    float acc[32];
#pragma unroll
    for (int q = 0; q < 32; q++) acc[q] = 0.f;
    float shacc = 0.f;
    int beg = g_off[n], end = g_off[n + 1];
    int is64 = g_e64;
    for (int j = beg; j < end; j++) {
        int e = g_sorted[j];
        long long s = ld_idx(eidx, e, is64);  // src
        if (t < 64) hid_s[t] = g_hidden[(size_t)e * HH + t];
        else        hsrc_s[t - 64] = g_hx[(size_t)s * HH + (t - 64)];
        __syncthreads();
        float c = hid_s[k];
        const float* hp = &hsrc_s[half * 32];
#pragma unroll
        for (int q = 0; q < 32; q++) acc[q] = fmaf(c, hp[q], acc[q]);
        if (t < 64) shacc += hsrc_s[t];
        __syncthreads();
    }
    size_t base = (size_t)n * KTOT;
#pragma unroll
    for (int q = 0; q < 32; q += 4) {
        float4 v = make_float4(acc[q], acc[q + 1], acc[q + 2], acc[q + 3]);
        *(float4*)&g_S[base + k * 64 + half * 32 + q] = v;
    }
    if (t < 64) g_S[base + 4096 + t] = shacc;
    else        g_S[base + 4160 + (t - 64)] = g_hx[(size_t)n * HH + (t - 64)];
}

// ---------------- GEMM: hx = lrelu(S @ Bcat + gc_bias)  [10000,4224]x[4224,64]
// BM=64, BN=64, BK=32. 256 threads, 4x4 outputs/thread, FFMA2 packed math.
// As stored TRANSPOSED [kk][m] (stride 68) -> conflict-free broadcast reads.
// Register prefetch of chunk c+1 overlaps DRAM latency with chunk c compute.
#define BK 32
#define NCHUNK (KTOT / BK)   // 132

__global__ __launch_bounds__(256) void k_gemm(const float* __restrict__ bias) {
    __shared__ float As[BK][68];   // [kk][m], stride 68 floats (16B-aligned rows)
    __shared__ float Bs[BK][64];   // [kk][o]
    int t = threadIdx.x;
    int m0 = blockIdx.x * 64;
    int tx = t & 15, ty = t >> 4;

    // accumulators: 4 rows x 4 cols as 4x2 f32x2 (column pairs)
    uint64_t accp[4][2];
#pragma unroll
    for (int i = 0; i < 4; i++) { accp[i][0] = 0ull; accp[i][1] = 0ull; }

    // A fill mapping: idx = t + 256*q (q=0,1) -> r = idx>>3 (0..63), c4 = idx&7
    int ar[2], ac4[2], aok[2];
#pragma unroll
    for (int q = 0; q < 2; q++) {
        int idx = t + 256 * q;
        ar[q] = idx >> 3;
        ac4[q] = idx & 7;
        aok[q] = (m0 + ar[q]) < GN;
    }
    // B fill mapping: kk = idx>>4 (0..31), c4 = idx&15
    float4 ra[2], rb[2];

    // prologue: load chunk 0
#pragma unroll
    for (int q = 0; q < 2; q++) {
        ra[q] = aok[q] ? *(const float4*)&g_S[(size_t)(m0 + ar[q]) * KTOT + ac4[q] * 4]
                       : make_float4(0.f, 0.f, 0.f, 0.f);
        int idx = t + 256 * q;
        rb[q] = *(const float4*)&g_Bcat[((idx >> 4)) * 64 + (idx & 15) * 4];
    }

    for (int c = 0; c < NCHUNK; c++) {
        __syncthreads();   // previous chunk's readers done
#pragma unroll
        for (int q = 0; q < 2; q++) {
            int kb = ac4[q] * 4;
            As[kb + 0][ar[q]] = ra[q].x;
            As[kb + 1][ar[q]] = ra[q].y;
            As[kb + 2][ar[q]] = ra[q].z;
            As[kb + 3][ar[q]] = ra[q].w;
            int idx = t + 256 * q;
            *(float4*)&Bs[idx >> 4][(idx & 15) * 4] = rb[q];
        }
        __syncthreads();

        // prefetch next chunk into registers
        if (c + 1 < NCHUNK) {
            int k0 = (c + 1) * BK;
#pragma unroll
            for (int q = 0; q < 2; q++) {
                ra[q] = aok[q] ? *(const float4*)&g_S[(size_t)(m0 + ar[q]) * KTOT + k0 + ac4[q] * 4]
                               : make_float4(0.f, 0.f, 0.f, 0.f);
                int idx = t + 256 * q;
                rb[q] = *(const float4*)&g_Bcat[(k0 + (idx >> 4)) * 64 + (idx & 15) * 4];
            }
        }

#pragma unroll
        for (int kk = 0; kk < BK; kk++) {
            float4 a = *(const float4*)&As[kk][ty * 4];
            float4 b = *(const float4*)&Bs[kk][tx * 4];
            uint64_t b01 = pack2(b.x, b.y);
            uint64_t b23 = pack2(b.z, b.w);
            uint64_t a0 = pack2(a.x, a.x);
            uint64_t a1 = pack2(a.y, a.y);
            uint64_t a2 = pack2(a.z, a.z);
            uint64_t a3 = pack2(a.w, a.w);
            ffma2(accp[0][0], a0, b01); ffma2(accp[0][1], a0, b23);
            ffma2(accp[1][0], a1, b01); ffma2(accp[1][1], a1, b23);
            ffma2(accp[2][0], a2, b01); ffma2(accp[2][1], a2, b23);
            ffma2(accp[3][0], a3, b01); ffma2(accp[3][1], a3, b23);
        }
    }

    // epilogue: bias + leaky relu
    int col = tx * 4;
    float b0 = bias[col + 0], b1 = bias[col + 1], b2 = bias[col + 2], b3 = bias[col + 3];
#pragma unroll
    for (int i = 0; i < 4; i++) {
        int row = m0 + ty * 4 + i;
        if (row < GN) {
            float v0, v1, v2, v3;
            unpack2(accp[i][0], v0, v1);
            unpack2(accp[i][1], v2, v3);
            float4 o;
            o.x = lrelu(v0 + b0);
            o.y = lrelu(v1 + b1);
            o.z = lrelu(v2 + b2);
            o.w = lrelu(v3 + b3);
            *(float4*)&g_hx[(size_t)row * HH + col] = o;
        }
    }
}

// ---------------- global_add_pool + head -------------------------------------
__global__ void k_pool(const void* batch) {
    int t = threadIdx.x;
    int n = blockIdx.x * 4 + (t >> 6);
    int o = t & 63;
    int g = (int)ld_idx(batch, n, g_b64);
    atomicAdd(&g_hg[g * HH + o], g_hx[(size_t)n * HH + o]);
}

__global__ void k_head(const float* __restrict__ fc1w, const float* __restrict__ fc1b,
                       const float* __restrict__ fc2w, const float* __restrict__ fc2b,
                       float* __restrict__ out) {
    int g = threadIdx.x;
    if (g >= GG) return;
    float h[64];
#pragma unroll
    for (int i = 0; i < 64; i++) h[i] = g_hg[g * 64 + i];
    float o = fc2b[0];
    for (int j = 0; j < 32; j++) {
        float s = fc1b[j];
#pragma unroll
        for (int i = 0; i < 64; i++) s = fmaf(h[i], fc1w[i * 32 + j], s);
        o = fmaf(lrelu(s), fc2w[j], o);
    }
    out[g] = o;
}

// ---------------- launch ------------------------------------------------------
extern "C" void kernel_launch(void* const* d_in, const int* in_sizes, int n_in,
                              void* d_out, int out_size) {
    const float* x     = (const float*)d_in[0];
    const void*  eidx  = d_in[1];
    const float* ea    = (const float*)d_in[2];
    const void*  batch = d_in[3];
    const float* nfc_w = (const float*)d_in[4];
    const float* nfc_b = (const float*)d_in[5];
    const float* e1w1  = (const float*)d_in[6];
    const float* e1b1  = (const float*)d_in[7];
    const float* e1w2  = (const float*)d_in[8];
    const float* e1b2  = (const float*)d_in[9];
    const float* g1root= (const float*)d_in[10];
    const float* g1bias= (const float*)d_in[11];
    const float* e2w1  = (const float*)d_in[12];
    const float* e2b1  = (const float*)d_in[13];
    const float* e2w2  = (const float*)d_in[14];
    const float* e2b2  = (const float*)d_in[15];
    const float* g2root= (const float*)d_in[16];
    const float* g2bias= (const float*)d_in[17];
    const float* fc1w  = (const float*)d_in[18];
    const float* fc1b  = (const float*)d_in[19];
    const float* fc2w  = (const float*)d_in[20];
    const float* fc2b  = (const float*)d_in[21];
    float* out = (float*)d_out;

    k_detect<<<1, 32>>>(eidx, batch);
    k_zero<<<(GN + 255) / 256, 256>>>();
    k_nodefc<<<GN / 4, 256>>>(x, nfc_w, nfc_b);
    k_hist<<<GE / 256, 256>>>(eidx);
    k_scan<<<1, 1024>>>();
    k_fill<<<GE / 256, 256>>>(eidx);
    k_sortnode<<<(GN + 127) / 128, 128>>>();

    // layer 1
    k_prepB<<<(KTOT * HH + 255) / 256, 256>>>(e1w2, e1b2, g1root);
    k_hidden<<<GE / 4, 256>>>(ea, e1w1, e1b1);
    k_S<<<GN, 128>>>(eidx);
    k_gemm<<<(GN + 63) / 64, 256>>>(g1bias);

    // layer 2
    k_prepB<<<(KTOT * HH + 255) / 256, 256>>>(e2w2, e2b2, g2root);
    k_hidden<<<GE / 4, 256>>>(ea, e2w1, e2b1);
    k_S<<<GN, 128>>>(eidx);
    k_gemm<<<(GN + 63) / 64, 256>>>(g2bias);

    k_pool<<<GN / 4, 256>>>(batch);
    k_head<<<1, 64>>>(fc1w, fc1b, fc2w, fc2b, out);
}